// round 8
// baseline (speedup 1.0000x reference)
#include <cuda_runtime.h>
#include <math.h>

#define NTOK 32768
#define CFEAT 64
#define NBLK 148          // persistent grid: one block per SM, all resident

// ---------------- scratch (static device memory; no allocation) ----------------
__device__ float g_t  [NTOK * CFEAT];   // tokens [n][c]
__device__ float g_hT [NTOK * CFEAT];   // channel-major [c][n]
__device__ float g_qs [NTOK * CFEAT];
__device__ float g_ks [NTOK * CFEAT];
__device__ float g_vs [NTOK * CFEAT];
__device__ int   g_idx3[3 * NTOK];
__device__ int   g_M3[3];
__device__ unsigned g_gen = 0;          // barrier generation (monotonic, wraps ok)
__device__ unsigned g_arrive = 0;       // arrival count (self-restoring)

// ---------------- software grid barrier (all NBLK blocks resident) -------------
__device__ __forceinline__ void grid_bar()
{
    __syncthreads();
    if (threadIdx.x == 0) {
        __threadfence();
        unsigned gen = *(volatile unsigned*)&g_gen;
        if (atomicAdd(&g_arrive, 1u) == NBLK - 1) {
            g_arrive = 0;
            __threadfence();
            atomicAdd(&g_gen, 1u);
        } else {
            while (*(volatile unsigned*)&g_gen == gen) __nanosleep(32);
        }
        __threadfence();
    }
    __syncthreads();
}

// ---------------- fused patch conv + pos embed + idx build ---------------------
// block b: z = b>>5, y = b&31, 32 tokens along x. Input = 16 contiguous rows
// of 128 floats -> fully coalesced float4 loads. Blocks 0..2 also build the
// dilation index lists (kernel boundary syncs them for the next kernel).
__global__ void __launch_bounds__(256) conv_pos_kernel(
    const float* __restrict__ x,
    const float* __restrict__ W,    // [64][64]
    const float* __restrict__ b,
    const float* __restrict__ pos)  // [64][32768]
{
    __shared__ float Praw[16][128];   // raw input rows [dz*4+dy][128]
    __shared__ float O[64][33];       // results [c][tok]
    int bid = blockIdx.x;
    int z   = bid >> 5, y = bid & 31;
    int n0  = bid * 32;               // == z*1024 + y*32
    int tid = threadIdx.x;

    // coalesced load: 512 float4 slots
    #pragma unroll
    for (int j = 0; j < 2; ++j) {
        int e    = tid + 256 * j;
        int row  = e >> 5;            // 0..15: dz = row>>2, dy = row&3
        int col4 = e & 31;
        const float4* src = (const float4*)(x
            + (size_t)(4*z + (row >> 2)) * 16384
            + (4*y + (row & 3)) * 128 + col4 * 4);
        *(float4*)&Praw[row][col4 * 4] = *src;
    }
    __syncthreads();

    int c = tid >> 2, sub = tid & 3;  // channel c; tokens sub + 4u
    float w[64];
    {
        const float4* wp = (const float4*)(W + c * 64);
        #pragma unroll
        for (int i = 0; i < 16; ++i) {
            float4 t4 = wp[i];
            w[4*i] = t4.x; w[4*i+1] = t4.y; w[4*i+2] = t4.z; w[4*i+3] = t4.w;
        }
    }
    float bv = b[c];
    float acc[8];
    #pragma unroll
    for (int u = 0; u < 8; ++u) acc[u] = bv;

    #pragma unroll
    for (int row = 0; row < 16; ++row) {          // row = dz*4+dy; k = row*4+dx
        #pragma unroll
        for (int u = 0; u < 8; ++u) {
            int tok = u * 4 + sub;
            float4 p = *(const float4*)&Praw[row][tok * 4];
            acc[u] += p.x * w[4*row];
            acc[u] += p.y * w[4*row+1];
            acc[u] += p.z * w[4*row+2];
            acc[u] += p.w * w[4*row+3];
        }
    }
    #pragma unroll
    for (int u = 0; u < 8; ++u) O[c][u * 4 + sub] = acc[u];
    __syncthreads();

    // add pos, write g_hT [c][n] coalesced
    #pragma unroll
    for (int j = 0; j < 8; ++j) {
        int e  = tid + 256 * j;
        int cc = e >> 5, nl = e & 31;
        float v = O[cc][nl] + pos[cc * NTOK + n0 + nl];
        O[cc][nl] = v;
        g_hT[cc * NTOK + n0 + nl] = v;
    }
    __syncthreads();

    // write g_t [n][c] coalesced
    #pragma unroll
    for (int j = 0; j < 8; ++j) {
        int e  = tid + 256 * j;
        int nl = e >> 6, cc = e & 63;
        g_t[(n0 + nl) * 64 + cc] = O[cc][nl];
    }

    // -------- blocks 0..2: dilation index build (numpy-f32-exact) --------------
    if (bid < 3) {
        __shared__ int scan[256];
        int dil = (bid == 0) ? 2 : (bid == 1) ? 4 : 6;
        int* out = g_idx3 + bid * NTOK;
        float fd = (float)dil;
        int base = tid * 128;

        unsigned long long fl0 = 0ull, fl1 = 0ull;
        int ccnt = 0;
        for (int j = 0; j < 128; ++j) {
            int n = base + j;
            int zz = (n >> 10) - 16, yy = ((n >> 5) & 31) - 16, xx = (n & 31) - 16;
            int ss = zz*zz + yy*yy + xx*xx;
            float d = sqrtf((float)ss);
            bool ok = (fmodf(d, fd) == 0.0f) || (ss == 0);
            if (ok) {
                if (j < 64) fl0 |= (1ull << j); else fl1 |= (1ull << (j - 64));
                ccnt++;
            }
        }
        scan[tid] = ccnt;
        __syncthreads();
        for (int off = 1; off < 256; off <<= 1) {
            int v = (tid >= off) ? scan[tid - off] : 0;
            __syncthreads();
            scan[tid] += v;
            __syncthreads();
        }
        int pos2 = scan[tid] - ccnt;
        for (int j = 0; j < 64; ++j)
            if (fl0 & (1ull << j)) out[pos2++] = base + j;
        for (int j = 0; j < 64; ++j)
            if (fl1 & (1ull << j)) out[pos2++] = base + 64 + j;
        if (tid == 255) g_M3[bid] = scan[255];
    }
}

// =================== persistent fused attention stack ==========================
// grid = NBLK x 512. Per dilation: QKV | bar | single-pass flash attn (+proj,
// residual, dual scatter) | bar. 5 grid barriers total.
__global__ void __launch_bounds__(512) fused_attn_kernel(
    const float* __restrict__ qkvw0, const float* __restrict__ qkvb0,
    const float* __restrict__ pw0,   const float* __restrict__ pb0,
    const float* __restrict__ qkvw1, const float* __restrict__ qkvb1,
    const float* __restrict__ pw1,   const float* __restrict__ pb1,
    const float* __restrict__ qkvw2, const float* __restrict__ qkvb2,
    const float* __restrict__ pw2,   const float* __restrict__ pb2)
{
    __shared__ float SM[160 * 68];            // 43.5 KB, re-aliased per stage

    int tid = threadIdx.x;
    int bid = blockIdx.x;

    const float* QW[3] = {qkvw0, qkvw1, qkvw2};
    const float* QB[3] = {qkvb0, qkvb1, qkvb2};
    const float* PW[3] = {pw0, pw1, pw2};
    const float* PB[3] = {pb0, pb1, pb2};

    for (int di = 0; di < 3; ++di) {
        int M = g_M3[di];
        const int* __restrict__ idx = g_idx3 + di * NTOK;
        int mtiles = (M + 31) >> 5;

        // ---------------- stage: QKV (scale 1/8 folded into Q) -----------------
        {
            float (*Ts)[68] = (float(*)[68])SM;
            const float* W  = QW[di];
            const float* bb = QB[di];

            int oc   = tid >> 1;          // 0..255 (valid < 192)
            int half = tid & 1;
            float w[64]; float bv = 0.f;
            if (oc < 192) {
                const float4* wr = (const float4*)(W + oc * 64);
                #pragma unroll
                for (int i = 0; i < 16; ++i) {
                    float4 t4 = wr[i];
                    w[4*i] = t4.x; w[4*i+1] = t4.y; w[4*i+2] = t4.z; w[4*i+3] = t4.w;
                }
                bv = bb[oc];
            }

            for (int mt = bid; mt < mtiles; mt += NBLK) {
                int m0 = mt * 32;
                __syncthreads();
                #pragma unroll
                for (int j = 0; j < 4; ++j) {
                    int e = tid + 512 * j;
                    int ml = e >> 6, k = e & 63;
                    int m = m0 + ml;
                    Ts[ml][k] = (m < M) ? g_t[idx[m] * 64 + k] : 0.f;
                }
                __syncthreads();
                if (oc < 192) {
                    int mmax = min(32, M - m0);
                    #pragma unroll
                    for (int g = 0; g < 2; ++g) {
                        int ml0 = half * 16 + g * 8;
                        float acc[8];
                        #pragma unroll
                        for (int u = 0; u < 8; ++u) acc[u] = bv;
                        #pragma unroll
                        for (int k4 = 0; k4 < 16; ++k4) {
                            #pragma unroll
                            for (int u = 0; u < 8; ++u) {
                                float4 t4 = *(const float4*)&Ts[ml0 + u][k4 * 4];
                                acc[u] += t4.x * w[4*k4];
                                acc[u] += t4.y * w[4*k4+1];
                                acc[u] += t4.z * w[4*k4+2];
                                acc[u] += t4.w * w[4*k4+3];
                            }
                        }
                        #pragma unroll
                        for (int u = 0; u < 8; ++u) {
                            int ml = ml0 + u;
                            if (ml < mmax) {
                                int m = m0 + ml;
                                if      (oc <  64) g_qs[m * 64 + oc]       = acc[u] * 0.125f;
                                else if (oc < 128) g_ks[m * 64 + oc - 64]  = acc[u];
                                else               g_vs[m * 64 + oc - 128] = acc[u];
                            }
                        }
                    }
                }
            }
        }
        grid_bar();

        // ---------- stage: single-pass flash attn + proj + resid + scatter -----
        {
            float (*Ksm)[68] = (float(*)[68])SM;
            float (*Vsm)[68] = (float(*)[68])(SM + 64 * 68);
            float (*Psm)[68] = (float(*)[68])(SM + 128 * 68);
            float (*Ysm)[68] = (float(*)[68])SM;      // alias Ksm after loop

            int r  = tid >> 4;        // query row 0..31
            int qq = tid & 15;        // lane in row
            int cb = qq * 4;          // 4 output channels

            for (int mt = bid; mt < mtiles; mt += NBLK) {
                int  m0    = mt * 32;
                int  m     = m0 + r;
                bool valid = (m < M);

                float qreg[64];
                {
                    const float4* qp = (const float4*)(g_qs + (valid ? m : m0) * 64);
                    #pragma unroll
                    for (int i = 0; i < 16; ++i) {
                        float4 v = qp[i];
                        qreg[4*i] = v.x; qreg[4*i+1] = v.y;
                        qreg[4*i+2] = v.z; qreg[4*i+3] = v.w;
                    }
                }
                float y[4] = {0.f, 0.f, 0.f, 0.f};
                float row_max = -1e30f, row_sum = 0.f;

                for (int n0 = 0; n0 < M; n0 += 64) {
                    __syncthreads();
                    #pragma unroll
                    for (int j = 0; j < 2; ++j) {
                        int e = tid + 512 * j;
                        int nl = e >> 4, k4 = e & 15;
                        int n = n0 + nl;
                        float4 kv = make_float4(0.f, 0.f, 0.f, 0.f);
                        float4 vv = kv;
                        if (n < M) {
                            kv = *(const float4*)(g_ks + n * 64 + k4 * 4);
                            vv = *(const float4*)(g_vs + n * 64 + k4 * 4);
                        }
                        *(float4*)&Ksm[nl][k4 * 4] = kv;
                        *(float4*)&Vsm[nl][k4 * 4] = vv;
                    }
                    __syncthreads();

                    float sc[4];
                    float tmax = -1e30f;
                    #pragma unroll
                    for (int kk = 0; kk < 4; ++kk) {
                        int nl = qq + 16 * kk;
                        float acc = 0.f;
                        #pragma unroll
                        for (int k4 = 0; k4 < 16; ++k4) {
                            float4 kvec = *(const float4*)&Ksm[nl][k4 * 4];
                            acc += qreg[4*k4]   * kvec.x;
                            acc += qreg[4*k4+1] * kvec.y;
                            acc += qreg[4*k4+2] * kvec.z;
                            acc += qreg[4*k4+3] * kvec.w;
                        }
                        if (n0 + nl >= M) acc = -1e30f;
                        sc[kk] = acc;
                        tmax = fmaxf(tmax, acc);
                    }
                    #pragma unroll
                    for (int o = 1; o < 16; o <<= 1)
                        tmax = fmaxf(tmax, __shfl_xor_sync(0xffffffffu, tmax, o));

                    float nmax = fmaxf(row_max, tmax);
                    float corr = __expf(row_max - nmax);
                    float lsum = 0.f;
                    #pragma unroll
                    for (int kk = 0; kk < 4; ++kk) {
                        float p = __expf(sc[kk] - nmax);
                        Psm[r][qq + 16 * kk] = p;
                        lsum += p;
                    }
                    #pragma unroll
                    for (int o = 1; o < 16; o <<= 1)
                        lsum += __shfl_xor_sync(0xffffffffu, lsum, o);
                    row_sum = row_sum * corr + lsum;
                    row_max = nmax;
                    #pragma unroll
                    for (int j = 0; j < 4; ++j) y[j] *= corr;
                    __syncwarp();

                    #pragma unroll 4
                    for (int nl = 0; nl < 64; ++nl) {
                        float p = Psm[r][nl];
                        float4 v0 = *(const float4*)&Vsm[nl][cb];
                        y[0] += p * v0.x; y[1] += p * v0.y;
                        y[2] += p * v0.z; y[3] += p * v0.w;
                    }
                }

                float inv = 1.0f / row_sum;
                __syncthreads();          // everyone done reading Ksm/Vsm
                *(float4*)&Ysm[r][cb] =
                    make_float4(y[0]*inv, y[1]*inv, y[2]*inv, y[3]*inv);
                __syncthreads();

                // proj + residual + dual scatter
                int oc = tid & 63;
                int rb = tid >> 6;        // 0..7
                float wrow[64];
                {
                    const float4* wr = (const float4*)(PW[di] + oc * 64);
                    #pragma unroll
                    for (int i = 0; i < 16; ++i) {
                        float4 v = wr[i];
                        wrow[4*i] = v.x; wrow[4*i+1] = v.y;
                        wrow[4*i+2] = v.z; wrow[4*i+3] = v.w;
                    }
                }
                float bv = PB[di][oc];
                int mmax = min(32, M - m0);
                for (int rr = rb; rr < mmax; rr += 8) {
                    float a0 = bv;
                    #pragma unroll
                    for (int k4 = 0; k4 < 16; ++k4) {
                        float4 y0 = *(const float4*)&Ysm[rr][k4 * 4];
                        a0 += y0.x * wrow[4*k4];
                        a0 += y0.y * wrow[4*k4+1];
                        a0 += y0.z * wrow[4*k4+2];
                        a0 += y0.w * wrow[4*k4+3];
                    }
                    a0 += Ysm[rr][oc];
                    int tok = idx[m0 + rr];
                    g_t [tok * 64 + oc]   = a0;
                    g_hT[oc * NTOK + tok] = a0;
                }
                __syncthreads();          // Ysm/Ksm reuse guard
            }
        }
        if (di < 2) grid_bar();
    }
}

// ---------------- trilinear x4 upsample: hT[c][32^3] -> out[c][128^3] ----------
__global__ void __launch_bounds__(256) upsample_kernel(float* __restrict__ out)
{
    const float S = 31.0f / 127.0f;
    int zo  = blockIdx.x;
    int c   = blockIdx.y;
    int tid = threadIdx.x;

    float pz = (float)zo * S;
    int z0 = (int)pz;
    int z1 = min(z0 + 1, 31);
    float wz = pz - (float)z0;

    __shared__ float F[1024];
    __shared__ float R[128][33];

    const float* p0 = g_hT + c * NTOK + z0 * 1024;
    const float* p1 = g_hT + c * NTOK + z1 * 1024;
    #pragma unroll
    for (int j = 0; j < 4; ++j) {
        int i = tid + 256 * j;
        float a = p0[i];
        F[i] = a + wz * (p1[i] - a);
    }
    __syncthreads();

    int w = tid >> 5, lane = tid & 31;

    #pragma unroll
    for (int j = 0; j < 16; ++j) {
        int yo = j * 8 + w;
        float py = (float)yo * S;
        int y0 = (int)py;
        int y1 = min(y0 + 1, 31);
        float wy = py - (float)y0;
        float a = F[y0 * 32 + lane];
        float b = F[y1 * 32 + lane];
        R[yo][lane] = a + wy * (b - a);
    }
    __syncthreads();

    int   x0[4], x1[4];
    float wx[4];
    #pragma unroll
    for (int j = 0; j < 4; ++j) {
        int xo = lane * 4 + j;
        float px = (float)xo * S;
        x0[j] = (int)px;
        x1[j] = min(x0[j] + 1, 31);
        wx[j] = px - (float)x0[j];
    }

    size_t obase = ((size_t)(c * 128 + zo)) * 16384;
    #pragma unroll
    for (int it = 0; it < 16; ++it) {
        int yo = it * 8 + w;
        const float* Rr = &R[yo][0];
        float4 o;
        #pragma unroll
        for (int j = 0; j < 4; ++j) {
            float r0 = Rr[x0[j]];
            (&o.x)[j] = r0 + wx[j] * (Rr[x1[j]] - r0);
        }
        __stcs((float4*)(out + obase + (size_t)yo * 128 + lane * 4), o);
    }
}

// ---------------- launch --------------------------------------------------------
extern "C" void kernel_launch(void* const* d_in, const int* in_sizes, int n_in,
                              void* d_out, int out_size)
{
    const float* x       = (const float*)d_in[0];
    const float* w_patch = (const float*)d_in[1];
    const float* b_patch = (const float*)d_in[2];
    const float* pos     = (const float*)d_in[3];

    conv_pos_kernel<<<NTOK / 32, 256>>>(x, w_patch, b_patch, pos);

    fused_attn_kernel<<<NBLK, 512>>>(
        (const float*)d_in[4],  (const float*)d_in[5],
        (const float*)d_in[6],  (const float*)d_in[7],
        (const float*)d_in[8],  (const float*)d_in[9],
        (const float*)d_in[10], (const float*)d_in[11],
        (const float*)d_in[12], (const float*)d_in[13],
        (const float*)d_in[14], (const float*)d_in[15]);

    upsample_kernel<<<dim3(128, 64), 256>>>((float*)d_out);
}

// round 9
// speedup vs baseline: 1.0492x; 1.0492x over previous
#include <cuda_runtime.h>
#include <math.h>

#define NTOK 32768
#define CFEAT 64
#define NBLK 32           // persistent grid for attn stack (all resident)

// ---------------- scratch (static device memory; no allocation) ----------------
__device__ float g_t  [NTOK * CFEAT];   // tokens [n][c]
__device__ float g_hT [NTOK * CFEAT];   // channel-major [c][n]
__device__ float g_qs [NTOK * CFEAT];
__device__ float g_ks [NTOK * CFEAT];
__device__ float g_vs [NTOK * CFEAT];
__device__ int   g_idx3[3 * NTOK];
__device__ int   g_M3[3];
__device__ unsigned g_gen = 0;          // barrier generation (monotonic, wraps ok)
__device__ unsigned g_arrive = 0;       // arrival count (self-restoring)

// ---------------- software grid barrier (all NBLK blocks resident) -------------
__device__ __forceinline__ void grid_bar()
{
    __syncthreads();
    if (threadIdx.x == 0) {
        __threadfence();
        unsigned gen = *(volatile unsigned*)&g_gen;
        if (atomicAdd(&g_arrive, 1u) == NBLK - 1) {
            g_arrive = 0;
            __threadfence();
            atomicAdd(&g_gen, 1u);
        } else {
            while (*(volatile unsigned*)&g_gen == gen) __nanosleep(32);
        }
        __threadfence();
    }
    __syncthreads();
}

// ---------------- fused patch conv + pos embed, dual-layout write --------------
// block b: z = b>>5, y = b&31, 32 tokens along x. Input = 16 contiguous rows
// of 128 floats -> fully coalesced float4 loads.
__global__ void __launch_bounds__(256) conv_pos_kernel(
    const float* __restrict__ x,
    const float* __restrict__ W,    // [64][64]
    const float* __restrict__ b,
    const float* __restrict__ pos)  // [64][32768]
{
    __shared__ float Praw[16][128];   // raw input rows [dz*4+dy][128]
    __shared__ float O[64][33];       // results [c][tok]
    int bid = blockIdx.x;
    int z   = bid >> 5, y = bid & 31;
    int n0  = bid * 32;               // == z*1024 + y*32
    int tid = threadIdx.x;

    // coalesced load: 512 float4 slots
    #pragma unroll
    for (int j = 0; j < 2; ++j) {
        int e    = tid + 256 * j;
        int row  = e >> 5;            // 0..15: dz = row>>2, dy = row&3
        int col4 = e & 31;
        const float4* src = (const float4*)(x
            + (size_t)(4*z + (row >> 2)) * 16384
            + (4*y + (row & 3)) * 128 + col4 * 4);
        *(float4*)&Praw[row][col4 * 4] = *src;
    }
    __syncthreads();

    int c = tid >> 2, sub = tid & 3;  // channel c; tokens sub + 4u
    float w[64];
    {
        const float4* wp = (const float4*)(W + c * 64);
        #pragma unroll
        for (int i = 0; i < 16; ++i) {
            float4 t4 = wp[i];
            w[4*i] = t4.x; w[4*i+1] = t4.y; w[4*i+2] = t4.z; w[4*i+3] = t4.w;
        }
    }
    float bv = b[c];
    float acc[8];
    #pragma unroll
    for (int u = 0; u < 8; ++u) acc[u] = bv;

    #pragma unroll
    for (int row = 0; row < 16; ++row) {          // row = dz*4+dy; k = row*4+dx
        #pragma unroll
        for (int u = 0; u < 8; ++u) {
            int tok = u * 4 + sub;
            float4 p = *(const float4*)&Praw[row][tok * 4];
            acc[u] += p.x * w[4*row];
            acc[u] += p.y * w[4*row+1];
            acc[u] += p.z * w[4*row+2];
            acc[u] += p.w * w[4*row+3];
        }
    }
    #pragma unroll
    for (int u = 0; u < 8; ++u) O[c][u * 4 + sub] = acc[u];
    __syncthreads();

    // add pos, write g_hT [c][n] coalesced
    #pragma unroll
    for (int j = 0; j < 8; ++j) {
        int e  = tid + 256 * j;
        int cc = e >> 5, nl = e & 31;
        float v = O[cc][nl] + pos[cc * NTOK + n0 + nl];
        O[cc][nl] = v;
        g_hT[cc * NTOK + n0 + nl] = v;
    }
    __syncthreads();

    // write g_t [n][c] coalesced
    #pragma unroll
    for (int j = 0; j < 8; ++j) {
        int e  = tid + 256 * j;
        int nl = e >> 6, cc = e & 63;
        g_t[(n0 + nl) * 64 + cc] = O[cc][nl];
    }
}

// =================== persistent fused attention stack ==========================
// grid = NBLK x 512. Stage 0: idx build (ss-table). Then per dilation:
// QKV | bar | single-pass flash attn (+proj, residual, dual scatter) | bar.
__global__ void __launch_bounds__(512) fused_attn_kernel(
    const float* __restrict__ qkvw0, const float* __restrict__ qkvb0,
    const float* __restrict__ pw0,   const float* __restrict__ pb0,
    const float* __restrict__ qkvw1, const float* __restrict__ qkvb1,
    const float* __restrict__ pw1,   const float* __restrict__ pb1,
    const float* __restrict__ qkvw2, const float* __restrict__ qkvb2,
    const float* __restrict__ pw2,   const float* __restrict__ pb2)
{
    __shared__ float SM[160 * 68];            // 43.5 KB, re-aliased per stage

    int tid = threadIdx.x;
    int bid = blockIdx.x;

    // ------------- stage 0: dilation index build via ss-validity table ---------
    if (bid < 3) {
        __shared__ int scan[512];
        __shared__ unsigned char valid[769];
        int dil = (bid == 0) ? 2 : (bid == 1) ? 4 : 6;
        int* out = g_idx3 + bid * NTOK;
        float fd = (float)dil;

        // table: identical math to the per-token reference (bit-exact)
        for (int ss = tid; ss < 769; ss += 512) {
            float d = sqrtf((float)ss);
            valid[ss] = ((fmodf(d, fd) == 0.0f) || (ss == 0)) ? 1 : 0;
        }
        __syncthreads();

        int base = tid * 64;
        unsigned long long fl = 0ull;
        int ccnt = 0;
        for (int j = 0; j < 64; ++j) {
            int n = base + j;
            int zz = (n >> 10) - 16, yy = ((n >> 5) & 31) - 16, xx = (n & 31) - 16;
            int ss = zz*zz + yy*yy + xx*xx;
            if (valid[ss]) { fl |= (1ull << j); ccnt++; }
        }
        scan[tid] = ccnt;
        __syncthreads();
        for (int off = 1; off < 512; off <<= 1) {
            int v = (tid >= off) ? scan[tid - off] : 0;
            __syncthreads();
            scan[tid] += v;
            __syncthreads();
        }
        int pos2 = scan[tid] - ccnt;
        for (int j = 0; j < 64; ++j)
            if (fl & (1ull << j)) out[pos2++] = base + j;
        if (tid == 511) g_M3[bid] = scan[511];
    }
    grid_bar();

    const float* QW[3] = {qkvw0, qkvw1, qkvw2};
    const float* QB[3] = {qkvb0, qkvb1, qkvb2};
    const float* PW[3] = {pw0, pw1, pw2};
    const float* PB[3] = {pb0, pb1, pb2};

    for (int di = 0; di < 3; ++di) {
        int M = g_M3[di];
        const int* __restrict__ idx = g_idx3 + di * NTOK;
        int mtiles = (M + 31) >> 5;

        // ---------------- stage: QKV (scale 1/8 folded into Q) -----------------
        {
            float (*Ts)[68] = (float(*)[68])SM;
            const float* W  = QW[di];
            const float* bb = QB[di];

            int oc   = tid >> 1;          // 0..255 (valid < 192)
            int half = tid & 1;
            float w[64]; float bv = 0.f;
            if (oc < 192) {
                const float4* wr = (const float4*)(W + oc * 64);
                #pragma unroll
                for (int i = 0; i < 16; ++i) {
                    float4 t4 = wr[i];
                    w[4*i] = t4.x; w[4*i+1] = t4.y; w[4*i+2] = t4.z; w[4*i+3] = t4.w;
                }
                bv = bb[oc];
            }

            for (int mt = bid; mt < mtiles; mt += NBLK) {
                int m0 = mt * 32;
                __syncthreads();
                #pragma unroll
                for (int j = 0; j < 4; ++j) {
                    int e = tid + 512 * j;
                    int ml = e >> 6, k = e & 63;
                    int m = m0 + ml;
                    Ts[ml][k] = (m < M) ? g_t[idx[m] * 64 + k] : 0.f;
                }
                __syncthreads();
                if (oc < 192) {
                    int mmax = min(32, M - m0);
                    #pragma unroll
                    for (int g = 0; g < 2; ++g) {
                        int ml0 = half * 16 + g * 8;
                        float acc[8];
                        #pragma unroll
                        for (int u = 0; u < 8; ++u) acc[u] = bv;
                        #pragma unroll
                        for (int k4 = 0; k4 < 16; ++k4) {
                            #pragma unroll
                            for (int u = 0; u < 8; ++u) {
                                float4 t4 = *(const float4*)&Ts[ml0 + u][k4 * 4];
                                acc[u] += t4.x * w[4*k4];
                                acc[u] += t4.y * w[4*k4+1];
                                acc[u] += t4.z * w[4*k4+2];
                                acc[u] += t4.w * w[4*k4+3];
                            }
                        }
                        #pragma unroll
                        for (int u = 0; u < 8; ++u) {
                            int ml = ml0 + u;
                            if (ml < mmax) {
                                int m = m0 + ml;
                                if      (oc <  64) g_qs[m * 64 + oc]       = acc[u] * 0.125f;
                                else if (oc < 128) g_ks[m * 64 + oc - 64]  = acc[u];
                                else               g_vs[m * 64 + oc - 128] = acc[u];
                            }
                        }
                    }
                }
            }
        }
        grid_bar();

        // ---------- stage: single-pass flash attn + proj + resid + scatter -----
        {
            float (*Ksm)[68] = (float(*)[68])SM;
            float (*Vsm)[68] = (float(*)[68])(SM + 64 * 68);
            float (*Psm)[68] = (float(*)[68])(SM + 128 * 68);
            float (*Ysm)[68] = (float(*)[68])SM;      // alias Ksm after loop

            int r  = tid >> 4;        // query row 0..31
            int qq = tid & 15;        // lane in row
            int cb = qq * 4;          // 4 output channels

            for (int mt = bid; mt < mtiles; mt += NBLK) {
                int  m0    = mt * 32;
                int  m     = m0 + r;
                bool valid = (m < M);

                float qreg[64];
                {
                    const float4* qp = (const float4*)(g_qs + (valid ? m : m0) * 64);
                    #pragma unroll
                    for (int i = 0; i < 16; ++i) {
                        float4 v = qp[i];
                        qreg[4*i] = v.x; qreg[4*i+1] = v.y;
                        qreg[4*i+2] = v.z; qreg[4*i+3] = v.w;
                    }
                }
                float y[4] = {0.f, 0.f, 0.f, 0.f};
                float row_max = -1e30f, row_sum = 0.f;

                for (int n0 = 0; n0 < M; n0 += 64) {
                    __syncthreads();
                    #pragma unroll
                    for (int j = 0; j < 2; ++j) {
                        int e = tid + 512 * j;
                        int nl = e >> 4, k4 = e & 15;
                        int n = n0 + nl;
                        float4 kv = make_float4(0.f, 0.f, 0.f, 0.f);
                        float4 vv = kv;
                        if (n < M) {
                            kv = *(const float4*)(g_ks + n * 64 + k4 * 4);
                            vv = *(const float4*)(g_vs + n * 64 + k4 * 4);
                        }
                        *(float4*)&Ksm[nl][k4 * 4] = kv;
                        *(float4*)&Vsm[nl][k4 * 4] = vv;
                    }
                    __syncthreads();

                    float sc[4];
                    float tmax = -1e30f;
                    #pragma unroll
                    for (int kk = 0; kk < 4; ++kk) {
                        int nl = qq + 16 * kk;
                        float acc = 0.f;
                        #pragma unroll
                        for (int k4 = 0; k4 < 16; ++k4) {
                            float4 kvec = *(const float4*)&Ksm[nl][k4 * 4];
                            acc += qreg[4*k4]   * kvec.x;
                            acc += qreg[4*k4+1] * kvec.y;
                            acc += qreg[4*k4+2] * kvec.z;
                            acc += qreg[4*k4+3] * kvec.w;
                        }
                        if (n0 + nl >= M) acc = -1e30f;
                        sc[kk] = acc;
                        tmax = fmaxf(tmax, acc);
                    }
                    #pragma unroll
                    for (int o = 1; o < 16; o <<= 1)
                        tmax = fmaxf(tmax, __shfl_xor_sync(0xffffffffu, tmax, o));

                    float nmax = fmaxf(row_max, tmax);
                    float corr = __expf(row_max - nmax);
                    float lsum = 0.f;
                    #pragma unroll
                    for (int kk = 0; kk < 4; ++kk) {
                        float p = __expf(sc[kk] - nmax);
                        Psm[r][qq + 16 * kk] = p;
                        lsum += p;
                    }
                    #pragma unroll
                    for (int o = 1; o < 16; o <<= 1)
                        lsum += __shfl_xor_sync(0xffffffffu, lsum, o);
                    row_sum = row_sum * corr + lsum;
                    row_max = nmax;
                    #pragma unroll
                    for (int j = 0; j < 4; ++j) y[j] *= corr;
                    __syncwarp();

                    #pragma unroll 4
                    for (int nl = 0; nl < 64; ++nl) {
                        float p = Psm[r][nl];
                        float4 v0 = *(const float4*)&Vsm[nl][cb];
                        y[0] += p * v0.x; y[1] += p * v0.y;
                        y[2] += p * v0.z; y[3] += p * v0.w;
                    }
                }

                float inv = 1.0f / row_sum;
                __syncthreads();          // everyone done reading Ksm/Vsm
                *(float4*)&Ysm[r][cb] =
                    make_float4(y[0]*inv, y[1]*inv, y[2]*inv, y[3]*inv);
                __syncthreads();

                // proj + residual + dual scatter
                int oc = tid & 63;
                int rb = tid >> 6;        // 0..7
                float wrow[64];
                {
                    const float4* wr = (const float4*)(PW[di] + oc * 64);
                    #pragma unroll
                    for (int i = 0; i < 16; ++i) {
                        float4 v = wr[i];
                        wrow[4*i] = v.x; wrow[4*i+1] = v.y;
                        wrow[4*i+2] = v.z; wrow[4*i+3] = v.w;
                    }
                }
                float bv = PB[di][oc];
                int mmax = min(32, M - m0);
                for (int rr = rb; rr < mmax; rr += 8) {
                    float a0 = bv;
                    #pragma unroll
                    for (int k4 = 0; k4 < 16; ++k4) {
                        float4 y0 = *(const float4*)&Ysm[rr][k4 * 4];
                        a0 += y0.x * wrow[4*k4];
                        a0 += y0.y * wrow[4*k4+1];
                        a0 += y0.z * wrow[4*k4+2];
                        a0 += y0.w * wrow[4*k4+3];
                    }
                    a0 += Ysm[rr][oc];
                    int tok = idx[m0 + rr];
                    g_t [tok * 64 + oc]   = a0;
                    g_hT[oc * NTOK + tok] = a0;
                }
                __syncthreads();          // Ysm/Ksm reuse guard
            }
        }
        if (di < 2) grid_bar();
    }
}

// ---------------- trilinear x4 upsample: hT[c][32^3] -> out[c][128^3] ----------
__global__ void __launch_bounds__(256) upsample_kernel(float* __restrict__ out)
{
    const float S = 31.0f / 127.0f;
    int zo  = blockIdx.x;
    int c   = blockIdx.y;
    int tid = threadIdx.x;

    float pz = (float)zo * S;
    int z0 = (int)pz;
    int z1 = min(z0 + 1, 31);
    float wz = pz - (float)z0;

    __shared__ float F[1024];
    __shared__ float R[128][33];

    const float* p0 = g_hT + c * NTOK + z0 * 1024;
    const float* p1 = g_hT + c * NTOK + z1 * 1024;
    #pragma unroll
    for (int j = 0; j < 4; ++j) {
        int i = tid + 256 * j;
        float a = p0[i];
        F[i] = a + wz * (p1[i] - a);
    }
    __syncthreads();

    int w = tid >> 5, lane = tid & 31;

    #pragma unroll
    for (int j = 0; j < 16; ++j) {
        int yo = j * 8 + w;
        float py = (float)yo * S;
        int y0 = (int)py;
        int y1 = min(y0 + 1, 31);
        float wy = py - (float)y0;
        float a = F[y0 * 32 + lane];
        float b = F[y1 * 32 + lane];
        R[yo][lane] = a + wy * (b - a);
    }
    __syncthreads();

    int   x0[4], x1[4];
    float wx[4];
    #pragma unroll
    for (int j = 0; j < 4; ++j) {
        int xo = lane * 4 + j;
        float px = (float)xo * S;
        x0[j] = (int)px;
        x1[j] = min(x0[j] + 1, 31);
        wx[j] = px - (float)x0[j];
    }

    size_t obase = ((size_t)(c * 128 + zo)) * 16384;
    #pragma unroll
    for (int it = 0; it < 16; ++it) {
        int yo = it * 8 + w;
        const float* Rr = &R[yo][0];
        float4 o;
        #pragma unroll
        for (int j = 0; j < 4; ++j) {
            float r0 = Rr[x0[j]];
            (&o.x)[j] = r0 + wx[j] * (Rr[x1[j]] - r0);
        }
        __stcs((float4*)(out + obase + (size_t)yo * 128 + lane * 4), o);
    }
}

// ---------------- launch --------------------------------------------------------
extern "C" void kernel_launch(void* const* d_in, const int* in_sizes, int n_in,
                              void* d_out, int out_size)
{
    const float* x       = (const float*)d_in[0];
    const float* w_patch = (const float*)d_in[1];
    const float* b_patch = (const float*)d_in[2];
    const float* pos     = (const float*)d_in[3];

    conv_pos_kernel<<<NTOK / 32, 256>>>(x, w_patch, b_patch, pos);

    fused_attn_kernel<<<NBLK, 512>>>(
        (const float*)d_in[4],  (const float*)d_in[5],
        (const float*)d_in[6],  (const float*)d_in[7],
        (const float*)d_in[8],  (const float*)d_in[9],
        (const float*)d_in[10], (const float*)d_in[11],
        (const float*)d_in[12], (const float*)d_in[13],
        (const float*)d_in[14], (const float*)d_in[15]);

    upsample_kernel<<<dim3(128, 64), 256>>>((float*)d_out);
}

// round 10
// speedup vs baseline: 1.0880x; 1.0370x over previous
#include <cuda_runtime.h>
#include <math.h>

#define NTOK 32768
#define CFEAT 64
#define NBLK 16           // persistent grid for attn stack (all resident)

// ---------------- scratch (static device memory; no allocation) ----------------
__device__ float g_t  [NTOK * CFEAT];   // tokens [n][c]
__device__ float g_hT [NTOK * CFEAT];   // channel-major [c][n]
__device__ float g_qs [NTOK * CFEAT];
__device__ float g_ks [NTOK * CFEAT];
__device__ float g_vs [NTOK * CFEAT];
__device__ int   g_idx3[3 * NTOK];
__device__ int   g_M3[3];
__device__ unsigned g_gen = 0;          // barrier generation (monotonic, wraps ok)
__device__ unsigned g_arrive = 0;       // arrival count (self-restoring)

// ---------------- software grid barrier (all NBLK blocks resident) -------------
__device__ __forceinline__ void grid_bar()
{
    __syncthreads();
    if (threadIdx.x == 0) {
        __threadfence();
        unsigned gen = *(volatile unsigned*)&g_gen;
        if (atomicAdd(&g_arrive, 1u) == NBLK - 1) {
            g_arrive = 0;
            __threadfence();
            atomicAdd(&g_gen, 1u);
        } else {
            while (*(volatile unsigned*)&g_gen == gen) {}
        }
        __threadfence();
    }
    __syncthreads();
}

// ---------------- dilation index build (ss-table, bit-exact vs numpy) ----------
__global__ void __launch_bounds__(256) build_idx_kernel()
{
    __shared__ unsigned char valid[769];
    __shared__ int scan[256];
    int bi  = blockIdx.x;
    int dil = (bi == 0) ? 2 : (bi == 1) ? 4 : 6;
    int* out = g_idx3 + bi * NTOK;
    int tid  = threadIdx.x;
    float fd = (float)dil;

    for (int ss = tid; ss < 769; ss += 256) {
        float d = sqrtf((float)ss);
        valid[ss] = ((fmodf(d, fd) == 0.0f) || (ss == 0)) ? 1 : 0;
    }
    __syncthreads();

    int base = tid * 128;
    unsigned long long fl0 = 0ull, fl1 = 0ull;
    int ccnt = 0;
    for (int j = 0; j < 128; ++j) {
        int n = base + j;
        int zz = (n >> 10) - 16, yy = ((n >> 5) & 31) - 16, xx = (n & 31) - 16;
        int ss = zz*zz + yy*yy + xx*xx;
        if (valid[ss]) {
            if (j < 64) fl0 |= (1ull << j); else fl1 |= (1ull << (j - 64));
            ccnt++;
        }
    }
    scan[tid] = ccnt;
    __syncthreads();
    for (int off = 1; off < 256; off <<= 1) {
        int v = (tid >= off) ? scan[tid - off] : 0;
        __syncthreads();
        scan[tid] += v;
        __syncthreads();
    }
    int pos = scan[tid] - ccnt;
    for (int j = 0; j < 64; ++j)
        if (fl0 & (1ull << j)) out[pos++] = base + j;
    for (int j = 0; j < 64; ++j)
        if (fl1 & (1ull << j)) out[pos++] = base + 64 + j;
    if (tid == 255) g_M3[bi] = scan[255];
}

// ---------------- fused patch conv + pos embed, dual-layout write --------------
// 256 blocks x 256 threads; block = 128 tokens (one z-plane row group: z, 4
// consecutive y, 32 x). Warp = 32 channels over identical tokens -> all compute
// LDS are single-wavefront broadcasts. Per-channel pos reads / hT writes are
// 512B contiguous.
__global__ void __launch_bounds__(256) conv_pos_kernel(
    const float* __restrict__ x,
    const float* __restrict__ W,    // [64][64]
    const float* __restrict__ b,
    const float* __restrict__ pos)  // [64][32768]
{
    __shared__ float S[128 * 68];     // phase1: Praw[64][128] (8192 f); phase2: O[128][68]
    int bid = blockIdx.x;
    int z   = bid >> 3, yq = bid & 7;
    int y0  = yq * 4;
    int n0  = z * 1024 + y0 * 32;     // 128 contiguous tokens n0..n0+127
    int tid = threadIdx.x;

    // ---- load 64 input rows of 128 floats (fully coalesced float4) ----
    #pragma unroll
    for (int j = 0; j < 8; ++j) {
        int e   = tid + 256 * j;
        int r   = e >> 5;             // 0..63: dz = r>>4, yloc = r&15
        int c4  = e & 31;
        const float4* src = (const float4*)(x
            + (size_t)(4*z + (r >> 4)) * 16384
            + (4*y0 + (r & 15)) * 128 + c4 * 4);
        *(float4*)&S[r * 128 + c4 * 4] = *src;
    }
    __syncthreads();

    // ---- GEMM: thread = channel ch x 32 tokens (one y row) ----
    int ch = tid & 63;
    int tg = tid >> 6;                // y row 0..3
    float w[64];
    {
        const float4* wp = (const float4*)(W + ch * 64);
        #pragma unroll
        for (int i = 0; i < 16; ++i) {
            float4 t4 = wp[i];
            w[4*i] = t4.x; w[4*i+1] = t4.y; w[4*i+2] = t4.z; w[4*i+3] = t4.w;
        }
    }
    float bv = b[ch];
    float acc[32];
    #pragma unroll
    for (int i = 0; i < 32; ++i) acc[i] = bv;

    #pragma unroll
    for (int k4 = 0; k4 < 16; ++k4) {         // k4 = dz*4+dy
        int row = (k4 >> 2) * 16 + tg * 4 + (k4 & 3);
        const float4* Pr = (const float4*)&S[row * 128];
        float wx = w[4*k4], wy = w[4*k4+1], wz2 = w[4*k4+2], ww = w[4*k4+3];
        #pragma unroll
        for (int i = 0; i < 32; ++i) {
            float4 p = Pr[i];                 // broadcast within warp
            acc[i] += p.x * wx;
            acc[i] += p.y * wy;
            acc[i] += p.z * wz2;
            acc[i] += p.w * ww;
        }
    }
    __syncthreads();                          // done with Praw

    // ---- store to O[t][ch] (stride 68; lanes=ch -> conflict-free) ----
    #pragma unroll
    for (int i = 0; i < 32; ++i)
        S[(tg * 32 + i) * 68 + ch] = acc[i];
    __syncthreads();

    // ---- pos add + g_hT write (lanes = token, coalesced 128B) ----
    #pragma unroll
    for (int rep = 0; rep < 32; ++rep) {
        int e  = tid + 256 * rep;             // 8192 elements
        int cc = e >> 7, t = e & 127;
        float v = S[t * 68 + cc] + pos[cc * NTOK + n0 + t];
        S[t * 68 + cc] = v;
        g_hT[cc * NTOK + n0 + t] = v;
    }
    __syncthreads();

    // ---- g_t write [n][c] via float4 ----
    #pragma unroll
    for (int j = 0; j < 8; ++j) {
        int e  = tid + 256 * j;               // 2048 float4
        int t  = e >> 4, c4 = e & 15;
        float4 v = *(const float4*)&S[t * 68 + c4 * 4];
        *(float4*)&g_t[(size_t)(n0 + t) * 64 + c4 * 4] = v;
    }
}

// =================== persistent fused attention stack ==========================
// grid = NBLK x 512. Per dilation: QKV | bar | flash attn (+proj/resid/scatter)
// | bar. 5 grid barriers total.
__global__ void __launch_bounds__(512) fused_attn_kernel(
    const float* __restrict__ qkvw0, const float* __restrict__ qkvb0,
    const float* __restrict__ pw0,   const float* __restrict__ pb0,
    const float* __restrict__ qkvw1, const float* __restrict__ qkvb1,
    const float* __restrict__ pw1,   const float* __restrict__ pb1,
    const float* __restrict__ qkvw2, const float* __restrict__ qkvb2,
    const float* __restrict__ pw2,   const float* __restrict__ pb2)
{
    __shared__ float SM[160 * 68];            // 43.5 KB, re-aliased per stage

    int tid = threadIdx.x;
    int bid = blockIdx.x;

    const float* QW[3] = {qkvw0, qkvw1, qkvw2};
    const float* QB[3] = {qkvb0, qkvb1, qkvb2};
    const float* PW[3] = {pw0, pw1, pw2};
    const float* PB[3] = {pb0, pb1, pb2};

    for (int di = 0; di < 3; ++di) {
        int M = g_M3[di];
        const int* __restrict__ idx = g_idx3 + di * NTOK;
        int mtiles = (M + 31) >> 5;

        // ---------------- stage: QKV (scale 1/8 folded into Q) -----------------
        {
            float (*Ts)[68] = (float(*)[68])SM;
            const float* W  = QW[di];
            const float* bb = QB[di];

            int oc   = tid >> 1;          // 0..255 (valid < 192)
            int half = tid & 1;
            float w[64]; float bv = 0.f;
            if (oc < 192) {
                const float4* wr = (const float4*)(W + oc * 64);
                #pragma unroll
                for (int i = 0; i < 16; ++i) {
                    float4 t4 = wr[i];
                    w[4*i] = t4.x; w[4*i+1] = t4.y; w[4*i+2] = t4.z; w[4*i+3] = t4.w;
                }
                bv = bb[oc];
            }

            for (int mt = bid; mt < mtiles; mt += NBLK) {
                int m0 = mt * 32;
                __syncthreads();
                #pragma unroll
                for (int j = 0; j < 4; ++j) {
                    int e = tid + 512 * j;
                    int ml = e >> 6, k = e & 63;
                    int m = m0 + ml;
                    Ts[ml][k] = (m < M) ? g_t[idx[m] * 64 + k] : 0.f;
                }
                __syncthreads();
                if (oc < 192) {
                    int mmax = min(32, M - m0);
                    #pragma unroll
                    for (int g = 0; g < 2; ++g) {
                        int ml0 = half * 16 + g * 8;
                        float acc[8];
                        #pragma unroll
                        for (int u = 0; u < 8; ++u) acc[u] = bv;
                        #pragma unroll
                        for (int k4 = 0; k4 < 16; ++k4) {
                            #pragma unroll
                            for (int u = 0; u < 8; ++u) {
                                float4 t4 = *(const float4*)&Ts[ml0 + u][k4 * 4];
                                acc[u] += t4.x * w[4*k4];
                                acc[u] += t4.y * w[4*k4+1];
                                acc[u] += t4.z * w[4*k4+2];
                                acc[u] += t4.w * w[4*k4+3];
                            }
                        }
                        #pragma unroll
                        for (int u = 0; u < 8; ++u) {
                            int ml = ml0 + u;
                            if (ml < mmax) {
                                int m = m0 + ml;
                                if      (oc <  64) g_qs[m * 64 + oc]       = acc[u] * 0.125f;
                                else if (oc < 128) g_ks[m * 64 + oc - 64]  = acc[u];
                                else               g_vs[m * 64 + oc - 128] = acc[u];
                            }
                        }
                    }
                }
            }
        }
        grid_bar();

        // ---------- stage: single-pass flash attn + proj + resid + scatter -----
        {
            float (*Ksm)[68] = (float(*)[68])SM;
            float (*Vsm)[68] = (float(*)[68])(SM + 64 * 68);
            float (*Psm)[68] = (float(*)[68])(SM + 128 * 68);
            float (*Ysm)[68] = (float(*)[68])SM;      // alias Ksm after loop

            int r  = tid >> 4;        // query row 0..31
            int qq = tid & 15;        // lane in row
            int cb = qq * 4;          // 4 output channels

            for (int mt = bid; mt < mtiles; mt += NBLK) {
                int  m0    = mt * 32;
                int  m     = m0 + r;
                bool valid = (m < M);

                float qreg[64];
                {
                    const float4* qp = (const float4*)(g_qs + (valid ? m : m0) * 64);
                    #pragma unroll
                    for (int i = 0; i < 16; ++i) {
                        float4 v = qp[i];
                        qreg[4*i] = v.x; qreg[4*i+1] = v.y;
                        qreg[4*i+2] = v.z; qreg[4*i+3] = v.w;
                    }
                }
                float y[4] = {0.f, 0.f, 0.f, 0.f};
                float row_max = -1e30f, row_sum = 0.f;

                for (int n0 = 0; n0 < M; n0 += 64) {
                    __syncthreads();
                    #pragma unroll
                    for (int j = 0; j < 2; ++j) {
                        int e = tid + 512 * j;
                        int nl = e >> 4, k4 = e & 15;
                        int n = n0 + nl;
                        float4 kv = make_float4(0.f, 0.f, 0.f, 0.f);
                        float4 vv = kv;
                        if (n < M) {
                            kv = *(const float4*)(g_ks + n * 64 + k4 * 4);
                            vv = *(const float4*)(g_vs + n * 64 + k4 * 4);
                        }
                        *(float4*)&Ksm[nl][k4 * 4] = kv;
                        *(float4*)&Vsm[nl][k4 * 4] = vv;
                    }
                    __syncthreads();

                    float sc[4];
                    float tmax = -1e30f;
                    #pragma unroll
                    for (int kk = 0; kk < 4; ++kk) {
                        int nl = qq + 16 * kk;
                        float acc = 0.f;
                        #pragma unroll
                        for (int k4 = 0; k4 < 16; ++k4) {
                            float4 kvec = *(const float4*)&Ksm[nl][k4 * 4];
                            acc += qreg[4*k4]   * kvec.x;
                            acc += qreg[4*k4+1] * kvec.y;
                            acc += qreg[4*k4+2] * kvec.z;
                            acc += qreg[4*k4+3] * kvec.w;
                        }
                        if (n0 + nl >= M) acc = -1e30f;
                        sc[kk] = acc;
                        tmax = fmaxf(tmax, acc);
                    }
                    #pragma unroll
                    for (int o = 1; o < 16; o <<= 1)
                        tmax = fmaxf(tmax, __shfl_xor_sync(0xffffffffu, tmax, o));

                    float nmax = fmaxf(row_max, tmax);
                    float corr = __expf(row_max - nmax);
                    float lsum = 0.f;
                    #pragma unroll
                    for (int kk = 0; kk < 4; ++kk) {
                        float p = __expf(sc[kk] - nmax);
                        Psm[r][qq + 16 * kk] = p;
                        lsum += p;
                    }
                    #pragma unroll
                    for (int o = 1; o < 16; o <<= 1)
                        lsum += __shfl_xor_sync(0xffffffffu, lsum, o);
                    row_sum = row_sum * corr + lsum;
                    row_max = nmax;
                    #pragma unroll
                    for (int j = 0; j < 4; ++j) y[j] *= corr;
                    __syncwarp();

                    #pragma unroll 4
                    for (int nl = 0; nl < 64; ++nl) {
                        float p = Psm[r][nl];
                        float4 v0 = *(const float4*)&Vsm[nl][cb];
                        y[0] += p * v0.x; y[1] += p * v0.y;
                        y[2] += p * v0.z; y[3] += p * v0.w;
                    }
                }

                float inv = 1.0f / row_sum;
                __syncthreads();          // everyone done reading Ksm/Vsm
                *(float4*)&Ysm[r][cb] =
                    make_float4(y[0]*inv, y[1]*inv, y[2]*inv, y[3]*inv);
                __syncthreads();

                // proj + residual + dual scatter
                int oc = tid & 63;
                int rb = tid >> 6;        // 0..7
                float wrow[64];
                {
                    const float4* wr = (const float4*)(PW[di] + oc * 64);
                    #pragma unroll
                    for (int i = 0; i < 16; ++i) {
                        float4 v = wr[i];
                        wrow[4*i] = v.x; wrow[4*i+1] = v.y;
                        wrow[4*i+2] = v.z; wrow[4*i+3] = v.w;
                    }
                }
                float bv = PB[di][oc];
                int mmax = min(32, M - m0);
                for (int rr = rb; rr < mmax; rr += 8) {
                    float a0 = bv;
                    #pragma unroll
                    for (int k4 = 0; k4 < 16; ++k4) {
                        float4 y0 = *(const float4*)&Ysm[rr][k4 * 4];
                        a0 += y0.x * wrow[4*k4];
                        a0 += y0.y * wrow[4*k4+1];
                        a0 += y0.z * wrow[4*k4+2];
                        a0 += y0.w * wrow[4*k4+3];
                    }
                    a0 += Ysm[rr][oc];
                    int tok = idx[m0 + rr];
                    g_t [tok * 64 + oc]   = a0;
                    g_hT[oc * NTOK + tok] = a0;
                }
                __syncthreads();          // Ysm/Ksm reuse guard
            }
        }
        if (di < 2) grid_bar();
    }
}

// ---------------- trilinear x4 upsample: hT[c][32^3] -> out[c][128^3] ----------
__global__ void __launch_bounds__(256) upsample_kernel(float* __restrict__ out)
{
    const float S = 31.0f / 127.0f;
    int zo  = blockIdx.x;
    int c   = blockIdx.y;
    int tid = threadIdx.x;

    float pz = (float)zo * S;
    int z0 = (int)pz;
    int z1 = min(z0 + 1, 31);
    float wz = pz - (float)z0;

    __shared__ float F[1024];
    __shared__ float R[128][33];

    const float* p0 = g_hT + c * NTOK + z0 * 1024;
    const float* p1 = g_hT + c * NTOK + z1 * 1024;
    #pragma unroll
    for (int j = 0; j < 4; ++j) {
        int i = tid + 256 * j;
        float a = p0[i];
        F[i] = a + wz * (p1[i] - a);
    }
    __syncthreads();

    int w = tid >> 5, lane = tid & 31;

    #pragma unroll
    for (int j = 0; j < 16; ++j) {
        int yo = j * 8 + w;
        float py = (float)yo * S;
        int y0 = (int)py;
        int y1 = min(y0 + 1, 31);
        float wy = py - (float)y0;
        float a = F[y0 * 32 + lane];
        float b = F[y1 * 32 + lane];
        R[yo][lane] = a + wy * (b - a);
    }
    __syncthreads();

    int   x0[4], x1[4];
    float wx[4];
    #pragma unroll
    for (int j = 0; j < 4; ++j) {
        int xo = lane * 4 + j;
        float px = (float)xo * S;
        x0[j] = (int)px;
        x1[j] = min(x0[j] + 1, 31);
        wx[j] = px - (float)x0[j];
    }

    size_t obase = ((size_t)(c * 128 + zo)) * 16384;
    #pragma unroll
    for (int it = 0; it < 16; ++it) {
        int yo = it * 8 + w;
        const float* Rr = &R[yo][0];
        float4 o;
        #pragma unroll
        for (int j = 0; j < 4; ++j) {
            float r0 = Rr[x0[j]];
            (&o.x)[j] = r0 + wx[j] * (Rr[x1[j]] - r0);
        }
        __stcs((float4*)(out + obase + (size_t)yo * 128 + lane * 4), o);
    }
}

// ---------------- launch --------------------------------------------------------
extern "C" void kernel_launch(void* const* d_in, const int* in_sizes, int n_in,
                              void* d_out, int out_size)
{
    const float* x       = (const float*)d_in[0];
    const float* w_patch = (const float*)d_in[1];
    const float* b_patch = (const float*)d_in[2];
    const float* pos     = (const float*)d_in[3];

    build_idx_kernel<<<3, 256>>>();
    conv_pos_kernel<<<256, 256>>>(x, w_patch, b_patch, pos);

    fused_attn_kernel<<<NBLK, 512>>>(
        (const float*)d_in[4],  (const float*)d_in[5],
        (const float*)d_in[6],  (const float*)d_in[7],
        (const float*)d_in[8],  (const float*)d_in[9],
        (const float*)d_in[10], (const float*)d_in[11],
        (const float*)d_in[12], (const float*)d_in[13],
        (const float*)d_in[14], (const float*)d_in[15]);

    upsample_kernel<<<dim3(128, 64), 256>>>((float*)d_out);
}